// round 15
// baseline (speedup 1.0000x reference)
#include <cuda_runtime.h>
#include <cuda_fp16.h>
#include <cstdint>
#include <stdint.h>
#include <math.h>

#define NB    512
#define NPG   128
#define EPG   2048
#define HID   128
#define KSEL  64

// ---- smem byte map (113,664 B, 2 CTAs/SM) ----
// Phase A / GEMM1: x0 hi@0 lo@18432 | W(chunk) hi@36864 lo@55296 (k-major 272B rows)
//                  | x1 hi@73728 lo@92160
// mid-GEMM1 (x0 dead): ATILE fp16 [128][256B swizzled] @0 (32KB) -- scatter target
// post-GEMM1: B tiles BHI@36864 BLO@71680 (272B rows); misc-late @32768
// post-GEMM2: B-tile region dead -> part2/pooled @36864
constexpr int MISCL = 32768;
constexpr int WHIo  = 36864;
constexpr int WLOo  = 55296;
constexpr int BHIo  = 36864;
constexpr int BLOo  = 71680;
constexpr int XHI1  = 73728;
constexpr int MISCE = 110592;
constexpr int SMEM_BYTES = 113664;

__device__ __forceinline__ unsigned smem_u32(const void* p) {
    unsigned a;
    asm("{ .reg .u64 t; cvta.to.shared.u64 t, %1; cvt.u32.u64 %0, t; }" : "=r"(a) : "l"(p));
    return a;
}

#define LDSM4(r, addr) \
    asm volatile("ldmatrix.sync.aligned.m8n8.x4.shared.b16 {%0,%1,%2,%3}, [%4];" \
        : "=r"((r)[0]), "=r"((r)[1]), "=r"((r)[2]), "=r"((r)[3]) : "r"(addr))

#define LDSM4T(r, addr) \
    asm volatile("ldmatrix.sync.aligned.m8n8.x4.trans.shared.b16 {%0,%1,%2,%3}, [%4];" \
        : "=r"((r)[0]), "=r"((r)[1]), "=r"((r)[2]), "=r"((r)[3]) : "r"(addr))

#define MMA16816(c, a, b0, b1) \
    asm volatile("mma.sync.aligned.m16n8k16.row.col.f32.f16.f16.f32 " \
        "{%0,%1,%2,%3},{%4,%5,%6,%7},{%8,%9},{%0,%1,%2,%3};" \
        : "+f"((c)[0]), "+f"((c)[1]), "+f"((c)[2]), "+f"((c)[3]) \
        : "r"((a)[0]), "r"((a)[1]), "r"((a)[2]), "r"((a)[3]), "r"(b0), "r"(b1))

__device__ __forceinline__ unsigned pack_h2(float lo, float hi_) {
    unsigned r;
    asm("cvt.rn.f16x2.f32 %0, %1, %2;" : "=r"(r) : "f"(hi_), "f"(lo));
    return r;
}
__device__ __forceinline__ unsigned pack_hh(__half a, __half b) {
    return ((unsigned)__half_as_ushort(b) << 16) | (unsigned)__half_as_ushort(a);
}
// ATILE swizzled 16B-group index for (row d, group g)
__device__ __forceinline__ unsigned asw(unsigned g, unsigned d) {
    return (g & 8u) | ((g & 7u) ^ (d & 7u));
}

// ---------------- main fused kernel (single launch) ----------------
extern __shared__ float S[];

__global__ void __launch_bounds__(256, 2) sagpool_fused_kernel(
    const float* __restrict__ x,
    const int*   __restrict__ esrc,
    const int*   __restrict__ edst,
    const float* __restrict__ W1,
    const float* __restrict__ b1,
    const float* __restrict__ Ws,
    const float* __restrict__ bs,
    const float* __restrict__ Wlin,
    const float* __restrict__ blin,
    float*       __restrict__ out)
{
    const int g = blockIdx.x;
    const int t = threadIdx.x;
    const int lane = t & 31;
    const int warp = t >> 5;

    char*  Sb     = (char*)S;
    float* rinv   = (float*)(Sb + MISCE);
    float* b1s    = rinv + 128;
    float* wss    = b1s  + 128;
    int*   cnt    = (int*)(wss + 128);       // 512B spare in misc-early
    float* uvec   = (float*)(Sb + MISCL);
    float* score  = uvec  + 128;
    float* wsel   = score + 128;
    float* part   = wsel + 128;              // 256 floats
    float* part2  = (float*)(Sb + BHIo);     // 512 floats (dead B-tile region)
    float* pooled = part2 + 512;

    // ---- Phase A0: edge loads + degree counters ----
    const int ebase = g * EPG;
    int sl[8], dl[8];
#pragma unroll
    for (int e = 0; e < 8; e++) {
        int ei = ebase + t + e * 256;
        sl[e] = esrc[ei] & (NPG - 1);
        dl[e] = edst[ei] & (NPG - 1);
    }
    if (t < 128) cnt[t] = 0;
    __syncthreads();
#pragma unroll
    for (int e = 0; e < 8; e++) atomicAdd(&cnt[dl[e]], 1);

    // ---- Phase A1: x both chunks + W chunk 0 staged (overlaps atomics) ----
    const float* xg = x + (size_t)g * NPG * HID;
#pragma unroll 1
    for (int h = 0; h < 2; h++) {
        const unsigned xb = (unsigned)(h * XHI1);
#pragma unroll
        for (int i = 0; i < 8; i++) {
            int idx = t + i * 256;
            int row = idx >> 4, f4 = idx & 15;
            float4 v = *(const float4*)(xg + row * HID + h * 64 + f4 * 4);
            __half h0 = __float2half_rn(v.x), h1 = __float2half_rn(v.y);
            __half h2 = __float2half_rn(v.z), h3 = __float2half_rn(v.w);
            *(uint2*)(Sb + xb + row * 144 + f4 * 8) =
                make_uint2(pack_hh(h0, h1), pack_hh(h2, h3));
            *(uint2*)(Sb + xb + 18432 + row * 144 + f4 * 8) =
                make_uint2(pack_h2(v.x - __half2float(h0), v.y - __half2float(h1)),
                           pack_h2(v.z - __half2float(h2), v.w - __half2float(h3)));
        }
    }
    {   // W chunk 0: k-major [64 k][128 n], fp16 hi/lo, 272B rows (for ldmatrix.trans)
#pragma unroll
        for (int i = 0; i < 8; i++) {
            int idx4 = t + i * 256;            // 0..2047
            int k = idx4 >> 5, n4 = idx4 & 31;
            float4 v = *(const float4*)(W1 + k * 128 + n4 * 4);
            __half h0 = __float2half_rn(v.x), h1 = __float2half_rn(v.y);
            __half h2 = __float2half_rn(v.z), h3 = __float2half_rn(v.w);
            *(uint2*)(Sb + WHIo + k * 272 + n4 * 8) =
                make_uint2(pack_hh(h0, h1), pack_hh(h2, h3));
            *(uint2*)(Sb + WLOo + k * 272 + n4 * 8) =
                make_uint2(pack_h2(v.x - __half2float(h0), v.y - __half2float(h1)),
                           pack_h2(v.z - __half2float(h2), v.w - __half2float(h3)));
        }
    }
    if (t < 128) { b1s[t] = b1[t]; wss[t] = Ws[t]; }
    __syncthreads();
    // degrees final -> rinv (consumers read after later syncs)
    if (t < 128) rinv[t] = rsqrtf((float)(cnt[t] + 1));

    // ---- Phase B: GEMM1 hp = x@W1 (fp16 3-term split); ATILE built between chunks ----
    const int m0 = (warp & 3) * 32;
    const int n0 = (warp >> 2) * 64;
    const unsigned q = (unsigned)lane >> 3, r8 = (unsigned)lane & 7;
    const unsigned qh = q >> 1;
    const unsigned SMB = smem_u32(S);

    const unsigned rowA = (m0 + (q & 1) * 8 + r8) * 144 + (q >> 1) * 16;
    const unsigned bTW = ((q & 1) * 8 + r8) * 272u + (unsigned)(n0 + ((q >> 1) & 1) * 8) * 2u;
    const unsigned bHiB = SMB + WHIo + bTW;
    const unsigned bLoB = SMB + WLOo + bTW;

    float acc[2][8][4];
#pragma unroll
    for (int mt = 0; mt < 2; mt++)
#pragma unroll
        for (int nt = 0; nt < 8; nt++)
#pragma unroll
            for (int i = 0; i < 4; i++) acc[mt][nt][i] = 0.f;

#pragma unroll 1
    for (int h = 0; h < 2; h++) {
        if (h == 1) {
            __syncthreads();                       // ch0 MMA reads done
            {
                int4 z = make_int4(0, 0, 0, 0);
                int4* az = (int4*)Sb;
                for (int i = t; i < 2048; i += 256) az[i] = z;
                // W chunk 1 restage (convert from W1 rows 64..127)
#pragma unroll
                for (int i = 0; i < 8; i++) {
                    int idx4 = t + i * 256;
                    int k = idx4 >> 5, n4 = idx4 & 31;
                    float4 v = *(const float4*)(W1 + (64 + k) * 128 + n4 * 4);
                    __half h0 = __float2half_rn(v.x), h1 = __float2half_rn(v.y);
                    __half h2 = __float2half_rn(v.z), h3 = __float2half_rn(v.w);
                    *(uint2*)(Sb + WHIo + k * 272 + n4 * 8) =
                        make_uint2(pack_hh(h0, h1), pack_hh(h2, h3));
                    *(uint2*)(Sb + WLOo + k * 272 + n4 * 8) =
                        make_uint2(pack_h2(v.x - __half2float(h0), v.y - __half2float(h1)),
                                   pack_h2(v.z - __half2float(h2), v.w - __half2float(h3)));
                }
            }
            __syncthreads();
            // scatter edges directly into fp16 ATILE (+1.0 each, exact)
            {
                const unsigned short one = 0x3C00;
#pragma unroll
                for (int e = 0; e < 8; e++) {
                    unsigned d = (unsigned)dl[e], s = (unsigned)sl[e];
                    unsigned addr = SMB + d * 256u + (asw(s >> 3, d) << 4) + (s & 7u) * 2u;
                    asm volatile("red.shared.add.noftz.f16 [%0], %1;"
                                 :: "r"(addr), "h"(one) : "memory");
                }
            }
            __syncthreads();                       // scatter visible before ch1
        }
        const unsigned aHi0 = SMB + (unsigned)(h * XHI1) + rowA;
        const unsigned aHi1 = aHi0 + 16 * 144;
        const unsigned aLo0 = aHi0 + 18432u;
        const unsigned aLo1 = aHi1 + 18432u;
#pragma unroll
        for (int kk = 0; kk < 4; kk++) {
            const unsigned ko  = (unsigned)kk * 32u;
            const unsigned bko = (unsigned)(kk * 16 * 272);
            unsigned ah0[4], ah1[4], al0[4], al1[4];
            LDSM4(ah0, aHi0 + ko);
            LDSM4(ah1, aHi1 + ko);
            LDSM4(al0, aLo0 + ko);
            LDSM4(al1, aLo1 + ko);
#pragma unroll
            for (int p = 0; p < 4; p++) {
                unsigned bh[4], bl[4];
                LDSM4T(bh, bHiB + bko + p * 32);
                LDSM4T(bl, bLoB + bko + p * 32);
                MMA16816(acc[0][2 * p],     ah0, bh[0], bh[1]);
                MMA16816(acc[0][2 * p + 1], ah0, bh[2], bh[3]);
                MMA16816(acc[1][2 * p],     ah1, bh[0], bh[1]);
                MMA16816(acc[1][2 * p + 1], ah1, bh[2], bh[3]);
                MMA16816(acc[0][2 * p],     al0, bh[0], bh[1]);
                MMA16816(acc[0][2 * p + 1], al0, bh[2], bh[3]);
                MMA16816(acc[1][2 * p],     al1, bh[0], bh[1]);
                MMA16816(acc[1][2 * p + 1], al1, bh[2], bh[3]);
                MMA16816(acc[0][2 * p],     ah0, bl[0], bl[1]);
                MMA16816(acc[0][2 * p + 1], ah0, bl[2], bl[3]);
                MMA16816(acc[1][2 * p],     ah1, bl[0], bl[1]);
                MMA16816(acc[1][2 * p + 1], ah1, bl[2], bl[3]);
            }
        }
    }
    // self-loop: ATILE = N + I (own-row write, race-free; scatter drained at last sync)
    if (t < 128) {
        __half* sp = (__half*)(Sb + t * 256 + (asw((unsigned)t >> 3, t) << 4) + (t & 7) * 2);
        *sp = __hadd(*sp, __float2half_rn(1.f));
    }
    __syncthreads();   // GEMM1 reads done + ATILE/rinv visible

    // ---- Phase C: hp' = rinv[s]*hp -> node-major [s][f] fp16 hi/lo, 272B rows ----
    {
        const int rb = lane >> 2, cb = 2 * (lane & 3);
#pragma unroll
        for (int mt = 0; mt < 2; mt++) {
            int row0 = m0 + 16 * mt + rb;
            float rv0 = rinv[row0], rv1 = rinv[row0 + 8];
#pragma unroll
            for (int nt = 0; nt < 8; nt++) {
                int col = n0 + 8 * nt + cb;
                float v0 = acc[mt][nt][0] * rv0, v1 = acc[mt][nt][1] * rv0;
                float v2 = acc[mt][nt][2] * rv1, v3 = acc[mt][nt][3] * rv1;
                __half h0 = __float2half_rn(v0), h1 = __float2half_rn(v1);
                __half h2 = __float2half_rn(v2), h3 = __float2half_rn(v3);
                unsigned o0 = row0 * 272u + col * 2u;
                unsigned o1 = (row0 + 8) * 272u + col * 2u;
                *(unsigned*)(Sb + BHIo + o0) = pack_hh(h0, h1);
                *(unsigned*)(Sb + BHIo + o1) = pack_hh(h2, h3);
                *(unsigned*)(Sb + BLOo + o0) =
                    pack_h2(v0 - __half2float(h0), v1 - __half2float(h1));
                *(unsigned*)(Sb + BLOo + o1) =
                    pack_h2(v2 - __half2float(h2), v3 - __half2float(h3));
            }
        }
    }
    __syncthreads();

    // ---- Phase E: GEMM2 = (N+I) @ hp' — rinv[d] epilogue scale makes this the
    //      exact GCN aggregate (diagonal supplies the self-loop term) ----
    const unsigned rA0 = (unsigned)(m0 + (q & 1) * 8 + r8);
    const unsigned rA1 = rA0 + 16;
    const unsigned bT = ((q & 1) * 8 + r8) * 272u + (unsigned)(n0 + ((q >> 1) & 1) * 8) * 2u;
    const unsigned bH2 = SMB + BHIo + bT;
    const unsigned bL2 = SMB + BLOo + bT;

    float acc2[2][8][4];
#pragma unroll
    for (int mt = 0; mt < 2; mt++)
#pragma unroll
        for (int nt = 0; nt < 8; nt++)
#pragma unroll
            for (int i = 0; i < 4; i++) acc2[mt][nt][i] = 0.f;

#pragma unroll
    for (int kk = 0; kk < 8; kk++) {
        const unsigned gA = (unsigned)(kk * 2) + qh;
        const unsigned addrA0 = SMB + rA0 * 256 + (asw(gA, rA0) << 4);
        const unsigned addrA1 = SMB + rA1 * 256 + (asw(gA, rA1) << 4);
        const unsigned bko = (unsigned)(kk * 16 * 272);
        unsigned a0[4], a1[4];
        LDSM4(a0, addrA0);
        LDSM4(a1, addrA1);
#pragma unroll
        for (int p = 0; p < 4; p++) {
            unsigned bh[4], bl[4];
            LDSM4T(bh, bH2 + bko + p * 32);
            LDSM4T(bl, bL2 + bko + p * 32);
            MMA16816(acc2[0][2 * p],     a0, bh[0], bh[1]);
            MMA16816(acc2[0][2 * p + 1], a0, bh[2], bh[3]);
            MMA16816(acc2[1][2 * p],     a1, bh[0], bh[1]);
            MMA16816(acc2[1][2 * p + 1], a1, bh[2], bh[3]);
            MMA16816(acc2[0][2 * p],     a0, bl[0], bl[1]);
            MMA16816(acc2[0][2 * p + 1], a0, bl[2], bl[3]);
            MMA16816(acc2[1][2 * p],     a1, bl[0], bl[1]);
            MMA16816(acc2[1][2 * p + 1], a1, bl[2], bl[3]);
        }
    }
    __syncthreads();   // GEMM2 reads done -> B tiles dead (part2/pooled live there)

    // ---- Phase F: epilogue in registers: acc2 = relu(rinv[d]*D + b1) + fused score GEMV ----
    {
        const int rb = lane >> 2, cb = 2 * (lane & 3);
        float tg[4] = {0.f, 0.f, 0.f, 0.f};
#pragma unroll
        for (int mt = 0; mt < 2; mt++) {
            int row0 = m0 + 16 * mt + rb;
            float rv0 = rinv[row0], rv1 = rinv[row0 + 8];
#pragma unroll
            for (int nt = 0; nt < 8; nt++) {
                int col = n0 + 8 * nt + cb;
                float bb0 = b1s[col], bb1 = b1s[col + 1];
                float w0 = wss[col], w1 = wss[col + 1];
                float v0 = fmaxf(fmaf(rv0, acc2[mt][nt][0], bb0), 0.f);
                float v1 = fmaxf(fmaf(rv0, acc2[mt][nt][1], bb1), 0.f);
                float v2 = fmaxf(fmaf(rv1, acc2[mt][nt][2], bb0), 0.f);
                float v3 = fmaxf(fmaf(rv1, acc2[mt][nt][3], bb1), 0.f);
                acc2[mt][nt][0] = v0; acc2[mt][nt][1] = v1;
                acc2[mt][nt][2] = v2; acc2[mt][nt][3] = v3;
                tg[mt * 2]     = fmaf(v0, w0, fmaf(v1, w1, tg[mt * 2]));
                tg[mt * 2 + 1] = fmaf(v2, w0, fmaf(v3, w1, tg[mt * 2 + 1]));
            }
        }
#pragma unroll
        for (int o = 1; o <= 2; o <<= 1) {
#pragma unroll
            for (int i = 0; i < 4; i++)
                tg[i] += __shfl_xor_sync(0xFFFFFFFFu, tg[i], o);
        }
        if ((lane & 3) == 0) {
            int half = (warp >> 2) * 128;
            part[half + m0 + rb]      = tg[0];
            part[half + m0 + 8 + rb]  = tg[1];
            part[half + m0 + 16 + rb] = tg[2];
            part[half + m0 + 24 + rb] = tg[3];
        }
    }
    __syncthreads();
    if (t < 128) uvec[t] = rinv[t] * (part[t] + part[t + 128]);
    __syncthreads();

    // ---- Phase H: score[d] = rinv[d]*<ATILE[d], uvec> + bs (2 accumulators) ----
    {
        int d = t & 127, hf = t >> 7;
        const char* rowb = Sb + d * 256;
        float a0 = 0.f, a1 = 0.f;
#pragma unroll
        for (int j = 0; j < 4; j++) {
#pragma unroll
            for (int half2i = 0; half2i < 2; half2i++) {
                int jj = (j + half2i * 4 + (d >> 3)) & 7;
                int gg = hf * 8 + jj;
                uint4 v = *(const uint4*)(rowb + (asw((unsigned)gg, (unsigned)d) << 4));
                const float* uv = uvec + gg * 8;
                float2 c0 = __half22float2(*(__half2*)&v.x);
                float2 c1 = __half22float2(*(__half2*)&v.y);
                float2 c2 = __half22float2(*(__half2*)&v.z);
                float2 c3 = __half22float2(*(__half2*)&v.w);
                float& a = half2i ? a1 : a0;
                a = fmaf(c0.x, uv[0], a); a = fmaf(c0.y, uv[1], a);
                a = fmaf(c1.x, uv[2], a); a = fmaf(c1.y, uv[3], a);
                a = fmaf(c2.x, uv[4], a); a = fmaf(c2.y, uv[5], a);
                a = fmaf(c3.x, uv[6], a); a = fmaf(c3.y, uv[7], a);
            }
        }
        part[t] = a0 + a1;
    }
    __syncthreads();
    if (t < 128)
        score[t] = rinv[t] * (part[t] + part[t + 128]) + bs[0];
    __syncthreads();

    // ---- Phase I: top-K rank (lax.top_k tie-break), 2 threads/row, 2 accumulators ----
    {
        int d = t & 127, hf = t >> 7;
        float sd = score[d];
        int rank0 = 0, rank1 = 0;
        const float4* sc4 = (const float4*)score + hf * 16;
#pragma unroll
        for (int j4 = 0; j4 < 8; j4++) {
            float4 s4 = sc4[j4];
            float4 s4b = sc4[j4 + 8];
            int j = (hf * 16 + j4) * 4;
            int jb = j + 32;
            rank0 += (s4.x > sd) || (s4.x == sd && j     < d);
            rank0 += (s4.y > sd) || (s4.y == sd && j + 1 < d);
            rank0 += (s4.z > sd) || (s4.z == sd && j + 2 < d);
            rank0 += (s4.w > sd) || (s4.w == sd && j + 3 < d);
            rank1 += (s4b.x > sd) || (s4b.x == sd && jb     < d);
            rank1 += (s4b.y > sd) || (s4b.y == sd && jb + 1 < d);
            rank1 += (s4b.z > sd) || (s4b.z == sd && jb + 2 < d);
            rank1 += (s4b.w > sd) || (s4b.w == sd && jb + 3 < d);
        }
        part[t] = (float)(rank0 + rank1);
    }
    __syncthreads();
    if (t < 128) {
        int rank = (int)(part[t] + part[t + 128]);
        wsel[t] = (rank < KSEL) ? (tanhf(score[t]) * (1.0f / KSEL)) : 0.0f;
    }
    __syncthreads();

    // ---- Phase J: pooled partials from registers (acc2 holds relu'd h) ----
    {
        const int rb = lane >> 2, cb = 2 * (lane & 3);
        float pp[8][2];
#pragma unroll
        for (int nt = 0; nt < 8; nt++) { pp[nt][0] = 0.f; pp[nt][1] = 0.f; }
#pragma unroll
        for (int mt = 0; mt < 2; mt++) {
            int row0 = m0 + 16 * mt + rb;
            float w0 = wsel[row0], w1 = wsel[row0 + 8];
#pragma unroll
            for (int nt = 0; nt < 8; nt++) {
                pp[nt][0] = fmaf(w0, acc2[mt][nt][0], fmaf(w1, acc2[mt][nt][2], pp[nt][0]));
                pp[nt][1] = fmaf(w0, acc2[mt][nt][1], fmaf(w1, acc2[mt][nt][3], pp[nt][1]));
            }
        }
#pragma unroll
        for (int o = 4; o <= 16; o <<= 1) {
#pragma unroll
            for (int nt = 0; nt < 8; nt++) {
                pp[nt][0] += __shfl_xor_sync(0xFFFFFFFFu, pp[nt][0], o);
                pp[nt][1] += __shfl_xor_sync(0xFFFFFFFFu, pp[nt][1], o);
            }
        }
        if (lane < 4) {
            float* dst = part2 + (warp & 3) * 128;
#pragma unroll
            for (int nt = 0; nt < 8; nt++) {
                int col = n0 + 8 * nt + cb;
                dst[col]     = pp[nt][0];
                dst[col + 1] = pp[nt][1];
            }
        }
    }
    __syncthreads();
    if (t < 128)
        pooled[t] = part2[t] + part2[128 + t] + part2[256 + t] + part2[384 + t];
    __syncthreads();

    // ---- Phase K: out = pooled @ Wlin + blin, 2 threads per f ----
    {
        int f = t & 127, hf = t >> 7;
        const float* pl = pooled + hf * 64;
        const float* wl = Wlin + hf * 64 * 128 + f;
        float o = 0.f;
#pragma unroll 16
        for (int k = 0; k < 64; k++) o = fmaf(pl[k], wl[k * 128], o);
        part[t] = o;
    }
    __syncthreads();
    if (t < 128)
        out[(size_t)g * HID + t] = part[t] + part[t + 128] + blin[t];
}

extern "C" void kernel_launch(void* const* d_in, const int* in_sizes, int n_in,
                              void* d_out, int out_size) {
    const float* x    = (const float*)d_in[0];
    const int*   ei   = (const int*)  d_in[1];
    const float* W1   = (const float*)d_in[3];
    const float* b1   = (const float*)d_in[4];
    const float* Ws   = (const float*)d_in[5];
    const float* bs   = (const float*)d_in[6];
    const float* Wlin = (const float*)d_in[7];
    const float* blin = (const float*)d_in[8];
    float* out = (float*)d_out;

    const int E = in_sizes[1] / 2;
    const int* esrc = ei;
    const int* edst = ei + E;

    cudaFuncSetAttribute(sagpool_fused_kernel,
                         cudaFuncAttributeMaxDynamicSharedMemorySize, SMEM_BYTES);
    sagpool_fused_kernel<<<NB, 256, SMEM_BYTES>>>(
        x, esrc, edst, W1, b1, Ws, bs, Wlin, blin, out);
}

// round 16
// speedup vs baseline: 1.0499x; 1.0499x over previous
#include <cuda_runtime.h>
#include <cuda_fp16.h>
#include <cstdint>
#include <stdint.h>
#include <math.h>

#define NB    512
#define NPG   128
#define EPG   2048
#define HID   128
#define KSEL  64

// ---- smem byte map (113,664 B, 2 CTAs/SM) ----
// Phase A / GEMM1: x0 hi@0 lo@18432 | W(chunk) hi@36864 lo@55296 (k-major 272B rows)
//                  | x1 hi@73728 lo@92160
// mid-GEMM1 (x0 dead): ATILE fp16 [128][256B swizzled] @0 (32KB) -- scatter target
// post-GEMM1: B tiles BHI@36864 BLO@71680 (272B rows); misc-late @32768
// post-GEMM2: B-tile region dead -> part2/pooled @36864
constexpr int MISCL = 32768;
constexpr int WHIo  = 36864;
constexpr int WLOo  = 55296;
constexpr int BHIo  = 36864;
constexpr int BLOo  = 71680;
constexpr int XHI1  = 73728;
constexpr int MISCE = 110592;
constexpr int SMEM_BYTES = 113664;

__device__ __forceinline__ unsigned smem_u32(const void* p) {
    unsigned a;
    asm("{ .reg .u64 t; cvta.to.shared.u64 t, %1; cvt.u32.u64 %0, t; }" : "=r"(a) : "l"(p));
    return a;
}

#define LDSM4(r, addr) \
    asm volatile("ldmatrix.sync.aligned.m8n8.x4.shared.b16 {%0,%1,%2,%3}, [%4];" \
        : "=r"((r)[0]), "=r"((r)[1]), "=r"((r)[2]), "=r"((r)[3]) : "r"(addr))

#define LDSM4T(r, addr) \
    asm volatile("ldmatrix.sync.aligned.m8n8.x4.trans.shared.b16 {%0,%1,%2,%3}, [%4];" \
        : "=r"((r)[0]), "=r"((r)[1]), "=r"((r)[2]), "=r"((r)[3]) : "r"(addr))

#define MMA16816(c, a, b0, b1) \
    asm volatile("mma.sync.aligned.m16n8k16.row.col.f32.f16.f16.f32 " \
        "{%0,%1,%2,%3},{%4,%5,%6,%7},{%8,%9},{%0,%1,%2,%3};" \
        : "+f"((c)[0]), "+f"((c)[1]), "+f"((c)[2]), "+f"((c)[3]) \
        : "r"((a)[0]), "r"((a)[1]), "r"((a)[2]), "r"((a)[3]), "r"(b0), "r"(b1))

__device__ __forceinline__ unsigned pack_h2(float lo, float hi_) {
    unsigned r;
    asm("cvt.rn.f16x2.f32 %0, %1, %2;" : "=r"(r) : "f"(hi_), "f"(lo));
    return r;
}
__device__ __forceinline__ unsigned pack_hh(__half a, __half b) {
    return ((unsigned)__half_as_ushort(b) << 16) | (unsigned)__half_as_ushort(a);
}
// ATILE swizzled 16B-group index for (row d, group g)
__device__ __forceinline__ unsigned asw(unsigned g, unsigned d) {
    return (g & 8u) | ((g & 7u) ^ (d & 7u));
}

// ---------------- main fused kernel (single launch) ----------------
extern __shared__ float S[];

__global__ void __launch_bounds__(256, 2) sagpool_fused_kernel(
    const float* __restrict__ x,
    const int*   __restrict__ esrc,
    const int*   __restrict__ edst,
    const float* __restrict__ W1,
    const float* __restrict__ b1,
    const float* __restrict__ Ws,
    const float* __restrict__ bs,
    const float* __restrict__ Wlin,
    const float* __restrict__ blin,
    float*       __restrict__ out)
{
    const int g = blockIdx.x;
    const int t = threadIdx.x;
    const int lane = t & 31;
    const int warp = t >> 5;

    char*  Sb     = (char*)S;
    float* rinv   = (float*)(Sb + MISCE);
    float* b1s    = rinv + 128;
    float* wss    = b1s  + 128;
    int*   cnt    = (int*)(wss + 128);       // 512B spare in misc-early
    float* uvec   = (float*)(Sb + MISCL);
    float* score  = uvec  + 128;
    float* wsel   = score + 128;
    float* part   = wsel + 128;              // 256 floats
    float* part2  = (float*)(Sb + BHIo);     // 512 floats (dead B-tile region)
    float* pooled = part2 + 512;

    // ---- Phase A0: edge loads + degree counters ----
    const int ebase = g * EPG;
    int sl[8], dl[8];
#pragma unroll
    for (int e = 0; e < 8; e++) {
        int ei = ebase + t + e * 256;
        sl[e] = esrc[ei] & (NPG - 1);
        dl[e] = edst[ei] & (NPG - 1);
    }
    if (t < 128) cnt[t] = 0;
    __syncthreads();
#pragma unroll
    for (int e = 0; e < 8; e++) atomicAdd(&cnt[dl[e]], 1);

    // ---- Phase A1: x both chunks + W chunk 0 staged (overlaps atomics) ----
    const float* xg = x + (size_t)g * NPG * HID;
#pragma unroll 1
    for (int h = 0; h < 2; h++) {
        const unsigned xb = (unsigned)(h * XHI1);
#pragma unroll
        for (int i = 0; i < 8; i++) {
            int idx = t + i * 256;
            int row = idx >> 4, f4 = idx & 15;
            float4 v = *(const float4*)(xg + row * HID + h * 64 + f4 * 4);
            __half h0 = __float2half_rn(v.x), h1 = __float2half_rn(v.y);
            __half h2 = __float2half_rn(v.z), h3 = __float2half_rn(v.w);
            *(uint2*)(Sb + xb + row * 144 + f4 * 8) =
                make_uint2(pack_hh(h0, h1), pack_hh(h2, h3));
            *(uint2*)(Sb + xb + 18432 + row * 144 + f4 * 8) =
                make_uint2(pack_h2(v.x - __half2float(h0), v.y - __half2float(h1)),
                           pack_h2(v.z - __half2float(h2), v.w - __half2float(h3)));
        }
    }
    {   // W chunk 0: k-major [64 k][128 n], fp16 hi/lo, 272B rows (for ldmatrix.trans)
#pragma unroll
        for (int i = 0; i < 8; i++) {
            int idx4 = t + i * 256;            // 0..2047
            int k = idx4 >> 5, n4 = idx4 & 31;
            float4 v = *(const float4*)(W1 + k * 128 + n4 * 4);
            __half h0 = __float2half_rn(v.x), h1 = __float2half_rn(v.y);
            __half h2 = __float2half_rn(v.z), h3 = __float2half_rn(v.w);
            *(uint2*)(Sb + WHIo + k * 272 + n4 * 8) =
                make_uint2(pack_hh(h0, h1), pack_hh(h2, h3));
            *(uint2*)(Sb + WLOo + k * 272 + n4 * 8) =
                make_uint2(pack_h2(v.x - __half2float(h0), v.y - __half2float(h1)),
                           pack_h2(v.z - __half2float(h2), v.w - __half2float(h3)));
        }
    }
    if (t < 128) { b1s[t] = b1[t]; wss[t] = Ws[t]; }
    __syncthreads();
    // degrees final -> rinv (consumers read after later syncs)
    if (t < 128) rinv[t] = rsqrtf((float)(cnt[t] + 1));

    // ---- Phase B: GEMM1 hp = x@W1 (fp16 3-term split); ATILE built between chunks ----
    const int m0 = (warp & 3) * 32;
    const int n0 = (warp >> 2) * 64;
    const unsigned q = (unsigned)lane >> 3, r8 = (unsigned)lane & 7;
    const unsigned qh = q >> 1;
    const unsigned SMB = smem_u32(S);

    const unsigned rowA = (m0 + (q & 1) * 8 + r8) * 144 + (q >> 1) * 16;
    const unsigned bTW = ((q & 1) * 8 + r8) * 272u + (unsigned)(n0 + ((q >> 1) & 1) * 8) * 2u;
    const unsigned bHiB = SMB + WHIo + bTW;
    const unsigned bLoB = SMB + WLOo + bTW;

    float acc[2][8][4];
#pragma unroll
    for (int mt = 0; mt < 2; mt++)
#pragma unroll
        for (int nt = 0; nt < 8; nt++)
#pragma unroll
            for (int i = 0; i < 4; i++) acc[mt][nt][i] = 0.f;

#pragma unroll 1
    for (int h = 0; h < 2; h++) {
        if (h == 1) {
            __syncthreads();                       // ch0 MMA reads done
            {
                int4 z = make_int4(0, 0, 0, 0);
                int4* az = (int4*)Sb;
                for (int i = t; i < 2048; i += 256) az[i] = z;
                // W chunk 1 restage (convert from W1 rows 64..127)
#pragma unroll
                for (int i = 0; i < 8; i++) {
                    int idx4 = t + i * 256;
                    int k = idx4 >> 5, n4 = idx4 & 31;
                    float4 v = *(const float4*)(W1 + (64 + k) * 128 + n4 * 4);
                    __half h0 = __float2half_rn(v.x), h1 = __float2half_rn(v.y);
                    __half h2 = __float2half_rn(v.z), h3 = __float2half_rn(v.w);
                    *(uint2*)(Sb + WHIo + k * 272 + n4 * 8) =
                        make_uint2(pack_hh(h0, h1), pack_hh(h2, h3));
                    *(uint2*)(Sb + WLOo + k * 272 + n4 * 8) =
                        make_uint2(pack_h2(v.x - __half2float(h0), v.y - __half2float(h1)),
                                   pack_h2(v.z - __half2float(h2), v.w - __half2float(h3)));
                }
            }
            __syncthreads();
            // scatter edges into fp16 ATILE (+1.0 each, exact); diag +1 folded in
            {
                const unsigned short one = 0x3C00;
#pragma unroll
                for (int e = 0; e < 8; e++) {
                    unsigned d = (unsigned)dl[e], s = (unsigned)sl[e];
                    unsigned addr = SMB + d * 256u + (asw(s >> 3, d) << 4) + (s & 7u) * 2u;
                    asm volatile("red.shared.add.noftz.f16 [%0], %1;"
                                 :: "r"(addr), "h"(one) : "memory");
                }
                if (t < 128) {   // self-loop: ATILE = N + I
                    unsigned dd = (unsigned)t;
                    unsigned addr = SMB + dd * 256u + (asw(dd >> 3, dd) << 4) + (dd & 7u) * 2u;
                    asm volatile("red.shared.add.noftz.f16 [%0], %1;"
                                 :: "r"(addr), "h"(one) : "memory");
                }
            }
            __syncthreads();                       // scatter visible before ch1
        }
        const unsigned aHi0 = SMB + (unsigned)(h * XHI1) + rowA;
        const unsigned aHi1 = aHi0 + 16 * 144;
        const unsigned aLo0 = aHi0 + 18432u;
        const unsigned aLo1 = aHi1 + 18432u;
#pragma unroll
        for (int kk = 0; kk < 4; kk++) {
            const unsigned ko  = (unsigned)kk * 32u;
            const unsigned bko = (unsigned)(kk * 16 * 272);
            unsigned ah0[4], ah1[4], al0[4], al1[4];
            LDSM4(ah0, aHi0 + ko);
            LDSM4(ah1, aHi1 + ko);
            LDSM4(al0, aLo0 + ko);
            LDSM4(al1, aLo1 + ko);
#pragma unroll
            for (int p = 0; p < 4; p++) {
                unsigned bh[4], bl[4];
                LDSM4T(bh, bHiB + bko + p * 32);
                LDSM4T(bl, bLoB + bko + p * 32);
                MMA16816(acc[0][2 * p],     ah0, bh[0], bh[1]);
                MMA16816(acc[0][2 * p + 1], ah0, bh[2], bh[3]);
                MMA16816(acc[1][2 * p],     ah1, bh[0], bh[1]);
                MMA16816(acc[1][2 * p + 1], ah1, bh[2], bh[3]);
                MMA16816(acc[0][2 * p],     al0, bh[0], bh[1]);
                MMA16816(acc[0][2 * p + 1], al0, bh[2], bh[3]);
                MMA16816(acc[1][2 * p],     al1, bh[0], bh[1]);
                MMA16816(acc[1][2 * p + 1], al1, bh[2], bh[3]);
                MMA16816(acc[0][2 * p],     ah0, bl[0], bl[1]);
                MMA16816(acc[0][2 * p + 1], ah0, bl[2], bl[3]);
                MMA16816(acc[1][2 * p],     ah1, bl[0], bl[1]);
                MMA16816(acc[1][2 * p + 1], ah1, bl[2], bl[3]);
            }
        }
    }
    __syncthreads();   // GEMM1 reads done + ATILE/rinv visible

    // ---- Phase C: hp' = rinv[s]*hp -> node-major [s][f] fp16 hi/lo, 272B rows ----
    {
        const int rb = lane >> 2, cb = 2 * (lane & 3);
#pragma unroll
        for (int mt = 0; mt < 2; mt++) {
            int row0 = m0 + 16 * mt + rb;
            float rv0 = rinv[row0], rv1 = rinv[row0 + 8];
#pragma unroll
            for (int nt = 0; nt < 8; nt++) {
                int col = n0 + 8 * nt + cb;
                float v0 = acc[mt][nt][0] * rv0, v1 = acc[mt][nt][1] * rv0;
                float v2 = acc[mt][nt][2] * rv1, v3 = acc[mt][nt][3] * rv1;
                __half h0 = __float2half_rn(v0), h1 = __float2half_rn(v1);
                __half h2 = __float2half_rn(v2), h3 = __float2half_rn(v3);
                unsigned o0 = row0 * 272u + col * 2u;
                unsigned o1 = (row0 + 8) * 272u + col * 2u;
                *(unsigned*)(Sb + BHIo + o0) = pack_hh(h0, h1);
                *(unsigned*)(Sb + BHIo + o1) = pack_hh(h2, h3);
                *(unsigned*)(Sb + BLOo + o0) =
                    pack_h2(v0 - __half2float(h0), v1 - __half2float(h1));
                *(unsigned*)(Sb + BLOo + o1) =
                    pack_h2(v2 - __half2float(h2), v3 - __half2float(h3));
            }
        }
    }
    __syncthreads();

    // ---- Phase E: GEMM2 = (N+I) @ hp' — rinv[d] epilogue scale makes this the
    //      exact GCN aggregate (diagonal supplies the self-loop term) ----
    const unsigned rA0 = (unsigned)(m0 + (q & 1) * 8 + r8);
    const unsigned rA1 = rA0 + 16;
    const unsigned bT = ((q & 1) * 8 + r8) * 272u + (unsigned)(n0 + ((q >> 1) & 1) * 8) * 2u;
    const unsigned bH2 = SMB + BHIo + bT;
    const unsigned bL2 = SMB + BLOo + bT;

    float acc2[2][8][4];
#pragma unroll
    for (int mt = 0; mt < 2; mt++)
#pragma unroll
        for (int nt = 0; nt < 8; nt++)
#pragma unroll
            for (int i = 0; i < 4; i++) acc2[mt][nt][i] = 0.f;

#pragma unroll
    for (int kk = 0; kk < 8; kk++) {
        const unsigned gA = (unsigned)(kk * 2) + qh;
        const unsigned addrA0 = SMB + rA0 * 256 + (asw(gA, rA0) << 4);
        const unsigned addrA1 = SMB + rA1 * 256 + (asw(gA, rA1) << 4);
        const unsigned bko = (unsigned)(kk * 16 * 272);
        unsigned a0[4], a1[4];
        LDSM4(a0, addrA0);
        LDSM4(a1, addrA1);
#pragma unroll
        for (int p = 0; p < 4; p++) {
            unsigned bh[4], bl[4];
            LDSM4T(bh, bH2 + bko + p * 32);
            LDSM4T(bl, bL2 + bko + p * 32);
            MMA16816(acc2[0][2 * p],     a0, bh[0], bh[1]);
            MMA16816(acc2[0][2 * p + 1], a0, bh[2], bh[3]);
            MMA16816(acc2[1][2 * p],     a1, bh[0], bh[1]);
            MMA16816(acc2[1][2 * p + 1], a1, bh[2], bh[3]);
            MMA16816(acc2[0][2 * p],     a0, bl[0], bl[1]);
            MMA16816(acc2[0][2 * p + 1], a0, bl[2], bl[3]);
            MMA16816(acc2[1][2 * p],     a1, bl[0], bl[1]);
            MMA16816(acc2[1][2 * p + 1], a1, bl[2], bl[3]);
        }
    }
    // NOTE: no barrier here — Phase F touches only registers and `part`
    // (misc gap 32768..36864), disjoint from GEMM2's smem reads (ATILE 0..32768,
    // B tiles 36864+); `part` is not read until after the next barrier.

    // ---- Phase F: epilogue in registers: acc2 = relu(rinv[d]*D + b1) + fused score GEMV ----
    {
        const int rb = lane >> 2, cb = 2 * (lane & 3);
        float tg[4] = {0.f, 0.f, 0.f, 0.f};
#pragma unroll
        for (int mt = 0; mt < 2; mt++) {
            int row0 = m0 + 16 * mt + rb;
            float rv0 = rinv[row0], rv1 = rinv[row0 + 8];
#pragma unroll
            for (int nt = 0; nt < 8; nt++) {
                int col = n0 + 8 * nt + cb;
                float bb0 = b1s[col], bb1 = b1s[col + 1];
                float w0 = wss[col], w1 = wss[col + 1];
                float v0 = fmaxf(fmaf(rv0, acc2[mt][nt][0], bb0), 0.f);
                float v1 = fmaxf(fmaf(rv0, acc2[mt][nt][1], bb1), 0.f);
                float v2 = fmaxf(fmaf(rv1, acc2[mt][nt][2], bb0), 0.f);
                float v3 = fmaxf(fmaf(rv1, acc2[mt][nt][3], bb1), 0.f);
                acc2[mt][nt][0] = v0; acc2[mt][nt][1] = v1;
                acc2[mt][nt][2] = v2; acc2[mt][nt][3] = v3;
                tg[mt * 2]     = fmaf(v0, w0, fmaf(v1, w1, tg[mt * 2]));
                tg[mt * 2 + 1] = fmaf(v2, w0, fmaf(v3, w1, tg[mt * 2 + 1]));
            }
        }
#pragma unroll
        for (int o = 1; o <= 2; o <<= 1) {
#pragma unroll
            for (int i = 0; i < 4; i++)
                tg[i] += __shfl_xor_sync(0xFFFFFFFFu, tg[i], o);
        }
        if ((lane & 3) == 0) {
            int half = (warp >> 2) * 128;
            part[half + m0 + rb]      = tg[0];
            part[half + m0 + 8 + rb]  = tg[1];
            part[half + m0 + 16 + rb] = tg[2];
            part[half + m0 + 24 + rb] = tg[3];
        }
    }
    __syncthreads();
    if (t < 128) uvec[t] = rinv[t] * (part[t] + part[t + 128]);
    __syncthreads();

    // ---- Phase H: score[d] = rinv[d]*<ATILE[d], uvec> + bs (2 accumulators) ----
    {
        int d = t & 127, hf = t >> 7;
        const char* rowb = Sb + d * 256;
        float a0 = 0.f, a1 = 0.f;
#pragma unroll
        for (int j = 0; j < 4; j++) {
#pragma unroll
            for (int half2i = 0; half2i < 2; half2i++) {
                int jj = (j + half2i * 4 + (d >> 3)) & 7;
                int gg = hf * 8 + jj;
                uint4 v = *(const uint4*)(rowb + (asw((unsigned)gg, (unsigned)d) << 4));
                const float* uv = uvec + gg * 8;
                float2 c0 = __half22float2(*(__half2*)&v.x);
                float2 c1 = __half22float2(*(__half2*)&v.y);
                float2 c2 = __half22float2(*(__half2*)&v.z);
                float2 c3 = __half22float2(*(__half2*)&v.w);
                float& a = half2i ? a1 : a0;
                a = fmaf(c0.x, uv[0], a); a = fmaf(c0.y, uv[1], a);
                a = fmaf(c1.x, uv[2], a); a = fmaf(c1.y, uv[3], a);
                a = fmaf(c2.x, uv[4], a); a = fmaf(c2.y, uv[5], a);
                a = fmaf(c3.x, uv[6], a); a = fmaf(c3.y, uv[7], a);
            }
        }
        part[t] = a0 + a1;
    }
    __syncthreads();
    if (t < 128)
        score[t] = rinv[t] * (part[t] + part[t + 128]) + bs[0];
    __syncthreads();

    // ---- Phase I: top-K rank (lax.top_k tie-break), 2 threads/row, 2 accumulators ----
    {
        int d = t & 127, hf = t >> 7;
        float sd = score[d];
        int rank0 = 0, rank1 = 0;
        const float4* sc4 = (const float4*)score + hf * 16;
#pragma unroll
        for (int j4 = 0; j4 < 8; j4++) {
            float4 s4 = sc4[j4];
            float4 s4b = sc4[j4 + 8];
            int j = (hf * 16 + j4) * 4;
            int jb = j + 32;
            rank0 += (s4.x > sd) || (s4.x == sd && j     < d);
            rank0 += (s4.y > sd) || (s4.y == sd && j + 1 < d);
            rank0 += (s4.z > sd) || (s4.z == sd && j + 2 < d);
            rank0 += (s4.w > sd) || (s4.w == sd && j + 3 < d);
            rank1 += (s4b.x > sd) || (s4b.x == sd && jb     < d);
            rank1 += (s4b.y > sd) || (s4b.y == sd && jb + 1 < d);
            rank1 += (s4b.z > sd) || (s4b.z == sd && jb + 2 < d);
            rank1 += (s4b.w > sd) || (s4b.w == sd && jb + 3 < d);
        }
        part[t] = (float)(rank0 + rank1);
    }
    __syncthreads();
    if (t < 128) {
        int rank = (int)(part[t] + part[t + 128]);
        wsel[t] = (rank < KSEL) ? (tanhf(score[t]) * (1.0f / KSEL)) : 0.0f;
    }
    __syncthreads();

    // ---- Phase J: pooled partials from registers (acc2 holds relu'd h) ----
    {
        const int rb = lane >> 2, cb = 2 * (lane & 3);
        float pp[8][2];
#pragma unroll
        for (int nt = 0; nt < 8; nt++) { pp[nt][0] = 0.f; pp[nt][1] = 0.f; }
#pragma unroll
        for (int mt = 0; mt < 2; mt++) {
            int row0 = m0 + 16 * mt + rb;
            float w0 = wsel[row0], w1 = wsel[row0 + 8];
#pragma unroll
            for (int nt = 0; nt < 8; nt++) {
                pp[nt][0] = fmaf(w0, acc2[mt][nt][0], fmaf(w1, acc2[mt][nt][2], pp[nt][0]));
                pp[nt][1] = fmaf(w0, acc2[mt][nt][1], fmaf(w1, acc2[mt][nt][3], pp[nt][1]));
            }
        }
#pragma unroll
        for (int o = 4; o <= 16; o <<= 1) {
#pragma unroll
            for (int nt = 0; nt < 8; nt++) {
                pp[nt][0] += __shfl_xor_sync(0xFFFFFFFFu, pp[nt][0], o);
                pp[nt][1] += __shfl_xor_sync(0xFFFFFFFFu, pp[nt][1], o);
            }
        }
        if (lane < 4) {
            float* dst = part2 + (warp & 3) * 128;
#pragma unroll
            for (int nt = 0; nt < 8; nt++) {
                int col = n0 + 8 * nt + cb;
                dst[col]     = pp[nt][0];
                dst[col + 1] = pp[nt][1];
            }
        }
    }
    __syncthreads();
    if (t < 128)
        pooled[t] = part2[t] + part2[128 + t] + part2[256 + t] + part2[384 + t];
    __syncthreads();

    // ---- Phase K: out = pooled @ Wlin + blin, 2 threads per f, dual chains ----
    {
        int f = t & 127, hf = t >> 7;
        const float* pl = pooled + hf * 64;
        const float* wl = Wlin + hf * 64 * 128 + f;
        float o0 = 0.f, o1 = 0.f;
#pragma unroll
        for (int k = 0; k < 32; k++) {
            o0 = fmaf(pl[k],      wl[k * 128],        o0);
            o1 = fmaf(pl[k + 32], wl[(k + 32) * 128], o1);
        }
        part[t] = o0 + o1;
    }
    __syncthreads();
    if (t < 128)
        out[(size_t)g * HID + t] = part[t] + part[t + 128] + blin[t];
}

extern "C" void kernel_launch(void* const* d_in, const int* in_sizes, int n_in,
                              void* d_out, int out_size) {
    const float* x    = (const float*)d_in[0];
    const int*   ei   = (const int*)  d_in[1];
    const float* W1   = (const float*)d_in[3];
    const float* b1   = (const float*)d_in[4];
    const float* Ws   = (const float*)d_in[5];
    const float* bs   = (const float*)d_in[6];
    const float* Wlin = (const float*)d_in[7];
    const float* blin = (const float*)d_in[8];
    float* out = (float*)d_out;

    const int E = in_sizes[1] / 2;
    const int* esrc = ei;
    const int* edst = ei + E;

    cudaFuncSetAttribute(sagpool_fused_kernel,
                         cudaFuncAttributeMaxDynamicSharedMemorySize, SMEM_BYTES);
    sagpool_fused_kernel<<<NB, 256, SMEM_BYTES>>>(
        x, esrc, edst, W1, b1, Ws, bs, Wlin, blin, out);
}

// round 17
// speedup vs baseline: 1.0506x; 1.0007x over previous
#include <cuda_runtime.h>
#include <cuda_fp16.h>
#include <cstdint>
#include <stdint.h>
#include <math.h>

#define NB    512
#define NPG   128
#define EPG   2048
#define HID   128
#define KSEL  64

// ---- smem byte map (113,664 B, 2 CTAs/SM) ----
// Phase A / GEMM1: x0 hi@0 lo@18432 | W(chunk) hi@36864 lo@55296 (k-major 272B rows)
//                  | x1 hi@73728 lo@92160
// mid-GEMM1 (x0 dead): ATILE fp16 [128][256B swizzled] @0 (32KB) -- scatter target
// post-GEMM1: B tiles BHI@36864 BLO@71680 (272B rows); misc-late @32768
// post-GEMM2: B-tile region dead -> part2/pooled @36864
constexpr int MISCL = 32768;
constexpr int WHIo  = 36864;
constexpr int WLOo  = 55296;
constexpr int BHIo  = 36864;
constexpr int BLOo  = 71680;
constexpr int XHI1  = 73728;
constexpr int MISCE = 110592;
constexpr int SMEM_BYTES = 113664;

__device__ __forceinline__ unsigned smem_u32(const void* p) {
    unsigned a;
    asm("{ .reg .u64 t; cvta.to.shared.u64 t, %1; cvt.u32.u64 %0, t; }" : "=r"(a) : "l"(p));
    return a;
}

#define LDSM4(r, addr) \
    asm volatile("ldmatrix.sync.aligned.m8n8.x4.shared.b16 {%0,%1,%2,%3}, [%4];" \
        : "=r"((r)[0]), "=r"((r)[1]), "=r"((r)[2]), "=r"((r)[3]) : "r"(addr))

#define LDSM4T(r, addr) \
    asm volatile("ldmatrix.sync.aligned.m8n8.x4.trans.shared.b16 {%0,%1,%2,%3}, [%4];" \
        : "=r"((r)[0]), "=r"((r)[1]), "=r"((r)[2]), "=r"((r)[3]) : "r"(addr))

#define MMA16816(c, a, b0, b1) \
    asm volatile("mma.sync.aligned.m16n8k16.row.col.f32.f16.f16.f32 " \
        "{%0,%1,%2,%3},{%4,%5,%6,%7},{%8,%9},{%0,%1,%2,%3};" \
        : "+f"((c)[0]), "+f"((c)[1]), "+f"((c)[2]), "+f"((c)[3]) \
        : "r"((a)[0]), "r"((a)[1]), "r"((a)[2]), "r"((a)[3]), "r"(b0), "r"(b1))

__device__ __forceinline__ unsigned pack_h2(float lo, float hi_) {
    unsigned r;
    asm("cvt.rn.f16x2.f32 %0, %1, %2;" : "=r"(r) : "f"(hi_), "f"(lo));
    return r;
}
__device__ __forceinline__ unsigned pack_hh(__half a, __half b) {
    return ((unsigned)__half_as_ushort(b) << 16) | (unsigned)__half_as_ushort(a);
}
// ATILE swizzled 16B-group index for (row d, group g)
__device__ __forceinline__ unsigned asw(unsigned g, unsigned d) {
    return (g & 8u) | ((g & 7u) ^ (d & 7u));
}

// ---------------- main fused kernel (single launch) ----------------
extern __shared__ float S[];

__global__ void __launch_bounds__(256, 2) sagpool_fused_kernel(
    const float* __restrict__ x,
    const int*   __restrict__ esrc,
    const int*   __restrict__ edst,
    const float* __restrict__ W1,
    const float* __restrict__ b1,
    const float* __restrict__ Ws,
    const float* __restrict__ bs,
    const float* __restrict__ Wlin,
    const float* __restrict__ blin,
    float*       __restrict__ out)
{
    const int g = blockIdx.x;
    const int t = threadIdx.x;
    const int lane = t & 31;
    const int warp = t >> 5;

    char*  Sb     = (char*)S;
    float* rinv   = (float*)(Sb + MISCE);
    float* b1s    = rinv + 128;
    float* wss    = b1s  + 128;
    int*   cnt    = (int*)(wss + 128);       // 512B spare in misc-early
    float* uvec   = (float*)(Sb + MISCL);
    float* score  = uvec  + 128;
    float* wsel   = score + 128;
    float* part   = wsel + 128;              // 256 floats
    float* part2  = (float*)(Sb + BHIo);     // 512 floats (dead B-tile region)
    float* pooled = part2 + 512;

    // ---- Phase A0: edge loads + degree counters ----
    const int ebase = g * EPG;
    int sl[8], dl[8];
#pragma unroll
    for (int e = 0; e < 8; e++) {
        int ei = ebase + t + e * 256;
        sl[e] = esrc[ei] & (NPG - 1);
        dl[e] = edst[ei] & (NPG - 1);
    }
    if (t < 128) cnt[t] = 0;
    __syncthreads();
#pragma unroll
    for (int e = 0; e < 8; e++) atomicAdd(&cnt[dl[e]], 1);

    // ---- Phase A1: x both chunks + W chunk 0 staged (overlaps atomics) ----
    const float* xg = x + (size_t)g * NPG * HID;
#pragma unroll 1
    for (int h = 0; h < 2; h++) {
        const unsigned xb = (unsigned)(h * XHI1);
#pragma unroll
        for (int i = 0; i < 8; i++) {
            int idx = t + i * 256;
            int row = idx >> 4, f4 = idx & 15;
            float4 v = *(const float4*)(xg + row * HID + h * 64 + f4 * 4);
            __half h0 = __float2half_rn(v.x), h1 = __float2half_rn(v.y);
            __half h2 = __float2half_rn(v.z), h3 = __float2half_rn(v.w);
            *(uint2*)(Sb + xb + row * 144 + f4 * 8) =
                make_uint2(pack_hh(h0, h1), pack_hh(h2, h3));
            *(uint2*)(Sb + xb + 18432 + row * 144 + f4 * 8) =
                make_uint2(pack_h2(v.x - __half2float(h0), v.y - __half2float(h1)),
                           pack_h2(v.z - __half2float(h2), v.w - __half2float(h3)));
        }
    }
    {   // W chunk 0: k-major [64 k][128 n], fp16 hi/lo, 272B rows (for ldmatrix.trans)
#pragma unroll
        for (int i = 0; i < 8; i++) {
            int idx4 = t + i * 256;            // 0..2047
            int k = idx4 >> 5, n4 = idx4 & 31;
            float4 v = *(const float4*)(W1 + k * 128 + n4 * 4);
            __half h0 = __float2half_rn(v.x), h1 = __float2half_rn(v.y);
            __half h2 = __float2half_rn(v.z), h3 = __float2half_rn(v.w);
            *(uint2*)(Sb + WHIo + k * 272 + n4 * 8) =
                make_uint2(pack_hh(h0, h1), pack_hh(h2, h3));
            *(uint2*)(Sb + WLOo + k * 272 + n4 * 8) =
                make_uint2(pack_h2(v.x - __half2float(h0), v.y - __half2float(h1)),
                           pack_h2(v.z - __half2float(h2), v.w - __half2float(h3)));
        }
    }
    if (t < 128) { b1s[t] = b1[t]; wss[t] = Ws[t]; }
    __syncthreads();
    // degrees final -> rinv (consumers read after later syncs)
    if (t < 128) rinv[t] = rsqrtf((float)(cnt[t] + 1));

    // ---- Phase B: GEMM1 hp = x@W1 (fp16 3-term split); ATILE built between chunks ----
    const int m0 = (warp & 3) * 32;
    const int n0 = (warp >> 2) * 64;
    const unsigned q = (unsigned)lane >> 3, r8 = (unsigned)lane & 7;
    const unsigned qh = q >> 1;
    const unsigned SMB = smem_u32(S);

    const unsigned rowA = (m0 + (q & 1) * 8 + r8) * 144 + (q >> 1) * 16;
    const unsigned bTW = ((q & 1) * 8 + r8) * 272u + (unsigned)(n0 + ((q >> 1) & 1) * 8) * 2u;
    const unsigned bHiB = SMB + WHIo + bTW;
    const unsigned bLoB = SMB + WLOo + bTW;

    float acc[2][8][4];
#pragma unroll
    for (int mt = 0; mt < 2; mt++)
#pragma unroll
        for (int nt = 0; nt < 8; nt++)
#pragma unroll
            for (int i = 0; i < 4; i++) acc[mt][nt][i] = 0.f;

#pragma unroll 1
    for (int h = 0; h < 2; h++) {
        if (h == 1) {
            __syncthreads();                       // ch0 MMA reads done
            {
                int4 z = make_int4(0, 0, 0, 0);
                int4* az = (int4*)Sb;
                for (int i = t; i < 2048; i += 256) az[i] = z;
                // W chunk 1 restage (convert from W1 rows 64..127)
#pragma unroll
                for (int i = 0; i < 8; i++) {
                    int idx4 = t + i * 256;
                    int k = idx4 >> 5, n4 = idx4 & 31;
                    float4 v = *(const float4*)(W1 + (64 + k) * 128 + n4 * 4);
                    __half h0 = __float2half_rn(v.x), h1 = __float2half_rn(v.y);
                    __half h2 = __float2half_rn(v.z), h3 = __float2half_rn(v.w);
                    *(uint2*)(Sb + WHIo + k * 272 + n4 * 8) =
                        make_uint2(pack_hh(h0, h1), pack_hh(h2, h3));
                    *(uint2*)(Sb + WLOo + k * 272 + n4 * 8) =
                        make_uint2(pack_h2(v.x - __half2float(h0), v.y - __half2float(h1)),
                                   pack_h2(v.z - __half2float(h2), v.w - __half2float(h3)));
                }
            }
            __syncthreads();                       // zero + W visible
            // scatter edges into fp16 ATILE (+1.0 each, exact); diag +1 folded in.
            // Fire-and-forget red.shared — OVERLAPS the ch1 MMA below (disjoint
            // smem: ATILE 0..32768 vs x1/W 36864+). Drained by the post-GEMM1
            // barrier before any ATILE reader (GEMM2 / Phase H).
            {
                const unsigned short one = 0x3C00;
#pragma unroll
                for (int e = 0; e < 8; e++) {
                    unsigned d = (unsigned)dl[e], s = (unsigned)sl[e];
                    unsigned addr = SMB + d * 256u + (asw(s >> 3, d) << 4) + (s & 7u) * 2u;
                    asm volatile("red.shared.add.noftz.f16 [%0], %1;"
                                 :: "r"(addr), "h"(one) : "memory");
                }
                if (t < 128) {   // self-loop: ATILE = N + I
                    unsigned dd = (unsigned)t;
                    unsigned addr = SMB + dd * 256u + (asw(dd >> 3, dd) << 4) + (dd & 7u) * 2u;
                    asm volatile("red.shared.add.noftz.f16 [%0], %1;"
                                 :: "r"(addr), "h"(one) : "memory");
                }
            }
        }
        const unsigned aHi0 = SMB + (unsigned)(h * XHI1) + rowA;
        const unsigned aHi1 = aHi0 + 16 * 144;
        const unsigned aLo0 = aHi0 + 18432u;
        const unsigned aLo1 = aHi1 + 18432u;
#pragma unroll
        for (int kk = 0; kk < 4; kk++) {
            const unsigned ko  = (unsigned)kk * 32u;
            const unsigned bko = (unsigned)(kk * 16 * 272);
            unsigned ah0[4], ah1[4], al0[4], al1[4];
            LDSM4(ah0, aHi0 + ko);
            LDSM4(ah1, aHi1 + ko);
            LDSM4(al0, aLo0 + ko);
            LDSM4(al1, aLo1 + ko);
#pragma unroll
            for (int p = 0; p < 4; p++) {
                unsigned bh[4], bl[4];
                LDSM4T(bh, bHiB + bko + p * 32);
                LDSM4T(bl, bLoB + bko + p * 32);
                MMA16816(acc[0][2 * p],     ah0, bh[0], bh[1]);
                MMA16816(acc[0][2 * p + 1], ah0, bh[2], bh[3]);
                MMA16816(acc[1][2 * p],     ah1, bh[0], bh[1]);
                MMA16816(acc[1][2 * p + 1], ah1, bh[2], bh[3]);
                MMA16816(acc[0][2 * p],     al0, bh[0], bh[1]);
                MMA16816(acc[0][2 * p + 1], al0, bh[2], bh[3]);
                MMA16816(acc[1][2 * p],     al1, bh[0], bh[1]);
                MMA16816(acc[1][2 * p + 1], al1, bh[2], bh[3]);
                MMA16816(acc[0][2 * p],     ah0, bl[0], bl[1]);
                MMA16816(acc[0][2 * p + 1], ah0, bl[2], bl[3]);
                MMA16816(acc[1][2 * p],     ah1, bl[0], bl[1]);
                MMA16816(acc[1][2 * p + 1], ah1, bl[2], bl[3]);
            }
        }
    }
    __syncthreads();   // GEMM1 reads done + scatter drained + rinv visible

    // ---- Phase C: hp' = rinv[s]*hp -> node-major [s][f] fp16 hi/lo, 272B rows ----
    {
        const int rb = lane >> 2, cb = 2 * (lane & 3);
#pragma unroll
        for (int mt = 0; mt < 2; mt++) {
            int row0 = m0 + 16 * mt + rb;
            float rv0 = rinv[row0], rv1 = rinv[row0 + 8];
#pragma unroll
            for (int nt = 0; nt < 8; nt++) {
                int col = n0 + 8 * nt + cb;
                float v0 = acc[mt][nt][0] * rv0, v1 = acc[mt][nt][1] * rv0;
                float v2 = acc[mt][nt][2] * rv1, v3 = acc[mt][nt][3] * rv1;
                __half h0 = __float2half_rn(v0), h1 = __float2half_rn(v1);
                __half h2 = __float2half_rn(v2), h3 = __float2half_rn(v3);
                unsigned o0 = row0 * 272u + col * 2u;
                unsigned o1 = (row0 + 8) * 272u + col * 2u;
                *(unsigned*)(Sb + BHIo + o0) = pack_hh(h0, h1);
                *(unsigned*)(Sb + BHIo + o1) = pack_hh(h2, h3);
                *(unsigned*)(Sb + BLOo + o0) =
                    pack_h2(v0 - __half2float(h0), v1 - __half2float(h1));
                *(unsigned*)(Sb + BLOo + o1) =
                    pack_h2(v2 - __half2float(h2), v3 - __half2float(h3));
            }
        }
    }
    __syncthreads();

    // ---- Phase E: GEMM2 = (N+I) @ hp' — rinv[d] epilogue scale makes this the
    //      exact GCN aggregate (diagonal supplies the self-loop term) ----
    const unsigned rA0 = (unsigned)(m0 + (q & 1) * 8 + r8);
    const unsigned rA1 = rA0 + 16;
    const unsigned bT = ((q & 1) * 8 + r8) * 272u + (unsigned)(n0 + ((q >> 1) & 1) * 8) * 2u;
    const unsigned bH2 = SMB + BHIo + bT;
    const unsigned bL2 = SMB + BLOo + bT;

    float acc2[2][8][4];
#pragma unroll
    for (int mt = 0; mt < 2; mt++)
#pragma unroll
        for (int nt = 0; nt < 8; nt++)
#pragma unroll
            for (int i = 0; i < 4; i++) acc2[mt][nt][i] = 0.f;

#pragma unroll
    for (int kk = 0; kk < 8; kk++) {
        const unsigned gA = (unsigned)(kk * 2) + qh;
        const unsigned addrA0 = SMB + rA0 * 256 + (asw(gA, rA0) << 4);
        const unsigned addrA1 = SMB + rA1 * 256 + (asw(gA, rA1) << 4);
        const unsigned bko = (unsigned)(kk * 16 * 272);
        unsigned a0[4], a1[4];
        LDSM4(a0, addrA0);
        LDSM4(a1, addrA1);
#pragma unroll
        for (int p = 0; p < 4; p++) {
            unsigned bh[4], bl[4];
            LDSM4T(bh, bH2 + bko + p * 32);
            LDSM4T(bl, bL2 + bko + p * 32);
            MMA16816(acc2[0][2 * p],     a0, bh[0], bh[1]);
            MMA16816(acc2[0][2 * p + 1], a0, bh[2], bh[3]);
            MMA16816(acc2[1][2 * p],     a1, bh[0], bh[1]);
            MMA16816(acc2[1][2 * p + 1], a1, bh[2], bh[3]);
            MMA16816(acc2[0][2 * p],     a0, bl[0], bl[1]);
            MMA16816(acc2[0][2 * p + 1], a0, bl[2], bl[3]);
            MMA16816(acc2[1][2 * p],     a1, bl[0], bl[1]);
            MMA16816(acc2[1][2 * p + 1], a1, bl[2], bl[3]);
        }
    }
    // no barrier: Phase F touches only registers + `part` (misc gap), disjoint
    // from GEMM2's smem reads; `part` is not read until after the next barrier.

    // ---- Phase F: epilogue in registers: acc2 = relu(rinv[d]*D + b1) + fused score GEMV ----
    {
        const int rb = lane >> 2, cb = 2 * (lane & 3);
        float tg[4] = {0.f, 0.f, 0.f, 0.f};
#pragma unroll
        for (int mt = 0; mt < 2; mt++) {
            int row0 = m0 + 16 * mt + rb;
            float rv0 = rinv[row0], rv1 = rinv[row0 + 8];
#pragma unroll
            for (int nt = 0; nt < 8; nt++) {
                int col = n0 + 8 * nt + cb;
                float bb0 = b1s[col], bb1 = b1s[col + 1];
                float w0 = wss[col], w1 = wss[col + 1];
                float v0 = fmaxf(fmaf(rv0, acc2[mt][nt][0], bb0), 0.f);
                float v1 = fmaxf(fmaf(rv0, acc2[mt][nt][1], bb1), 0.f);
                float v2 = fmaxf(fmaf(rv1, acc2[mt][nt][2], bb0), 0.f);
                float v3 = fmaxf(fmaf(rv1, acc2[mt][nt][3], bb1), 0.f);
                acc2[mt][nt][0] = v0; acc2[mt][nt][1] = v1;
                acc2[mt][nt][2] = v2; acc2[mt][nt][3] = v3;
                tg[mt * 2]     = fmaf(v0, w0, fmaf(v1, w1, tg[mt * 2]));
                tg[mt * 2 + 1] = fmaf(v2, w0, fmaf(v3, w1, tg[mt * 2 + 1]));
            }
        }
#pragma unroll
        for (int o = 1; o <= 2; o <<= 1) {
#pragma unroll
            for (int i = 0; i < 4; i++)
                tg[i] += __shfl_xor_sync(0xFFFFFFFFu, tg[i], o);
        }
        if ((lane & 3) == 0) {
            int half = (warp >> 2) * 128;
            part[half + m0 + rb]      = tg[0];
            part[half + m0 + 8 + rb]  = tg[1];
            part[half + m0 + 16 + rb] = tg[2];
            part[half + m0 + 24 + rb] = tg[3];
        }
    }
    __syncthreads();
    if (t < 128) uvec[t] = rinv[t] * (part[t] + part[t + 128]);
    __syncthreads();

    // ---- Phase H: score[d] = rinv[d]*<ATILE[d], uvec> + bs (2 accumulators) ----
    {
        int d = t & 127, hf = t >> 7;
        const char* rowb = Sb + d * 256;
        float a0 = 0.f, a1 = 0.f;
#pragma unroll
        for (int j = 0; j < 4; j++) {
#pragma unroll
            for (int half2i = 0; half2i < 2; half2i++) {
                int jj = (j + half2i * 4 + (d >> 3)) & 7;
                int gg = hf * 8 + jj;
                uint4 v = *(const uint4*)(rowb + (asw((unsigned)gg, (unsigned)d) << 4));
                const float* uv = uvec + gg * 8;
                float2 c0 = __half22float2(*(__half2*)&v.x);
                float2 c1 = __half22float2(*(__half2*)&v.y);
                float2 c2 = __half22float2(*(__half2*)&v.z);
                float2 c3 = __half22float2(*(__half2*)&v.w);
                float& a = half2i ? a1 : a0;
                a = fmaf(c0.x, uv[0], a); a = fmaf(c0.y, uv[1], a);
                a = fmaf(c1.x, uv[2], a); a = fmaf(c1.y, uv[3], a);
                a = fmaf(c2.x, uv[4], a); a = fmaf(c2.y, uv[5], a);
                a = fmaf(c3.x, uv[6], a); a = fmaf(c3.y, uv[7], a);
            }
        }
        part[t] = a0 + a1;
    }
    __syncthreads();
    if (t < 128)
        score[t] = rinv[t] * (part[t] + part[t + 128]) + bs[0];
    __syncthreads();

    // ---- Phase I: top-K rank (lax.top_k tie-break), 2 threads/row, 2 accumulators ----
    {
        int d = t & 127, hf = t >> 7;
        float sd = score[d];
        int rank0 = 0, rank1 = 0;
        const float4* sc4 = (const float4*)score + hf * 16;
#pragma unroll
        for (int j4 = 0; j4 < 8; j4++) {
            float4 s4 = sc4[j4];
            float4 s4b = sc4[j4 + 8];
            int j = (hf * 16 + j4) * 4;
            int jb = j + 32;
            rank0 += (s4.x > sd) || (s4.x == sd && j     < d);
            rank0 += (s4.y > sd) || (s4.y == sd && j + 1 < d);
            rank0 += (s4.z > sd) || (s4.z == sd && j + 2 < d);
            rank0 += (s4.w > sd) || (s4.w == sd && j + 3 < d);
            rank1 += (s4b.x > sd) || (s4b.x == sd && jb     < d);
            rank1 += (s4b.y > sd) || (s4b.y == sd && jb + 1 < d);
            rank1 += (s4b.z > sd) || (s4b.z == sd && jb + 2 < d);
            rank1 += (s4b.w > sd) || (s4b.w == sd && jb + 3 < d);
        }
        part[t] = (float)(rank0 + rank1);
    }
    __syncthreads();
    if (t < 128) {
        int rank = (int)(part[t] + part[t + 128]);
        wsel[t] = (rank < KSEL) ? (tanhf(score[t]) * (1.0f / KSEL)) : 0.0f;
    }
    __syncthreads();

    // ---- Phase J: pooled partials from registers (acc2 holds relu'd h) ----
    {
        const int rb = lane >> 2, cb = 2 * (lane & 3);
        float pp[8][2];
#pragma unroll
        for (int nt = 0; nt < 8; nt++) { pp[nt][0] = 0.f; pp[nt][1] = 0.f; }
#pragma unroll
        for (int mt = 0; mt < 2; mt++) {
            int row0 = m0 + 16 * mt + rb;
            float w0 = wsel[row0], w1 = wsel[row0 + 8];
#pragma unroll
            for (int nt = 0; nt < 8; nt++) {
                pp[nt][0] = fmaf(w0, acc2[mt][nt][0], fmaf(w1, acc2[mt][nt][2], pp[nt][0]));
                pp[nt][1] = fmaf(w0, acc2[mt][nt][1], fmaf(w1, acc2[mt][nt][3], pp[nt][1]));
            }
        }
#pragma unroll
        for (int o = 4; o <= 16; o <<= 1) {
#pragma unroll
            for (int nt = 0; nt < 8; nt++) {
                pp[nt][0] += __shfl_xor_sync(0xFFFFFFFFu, pp[nt][0], o);
                pp[nt][1] += __shfl_xor_sync(0xFFFFFFFFu, pp[nt][1], o);
            }
        }
        if (lane < 4) {
            float* dst = part2 + (warp & 3) * 128;
#pragma unroll
            for (int nt = 0; nt < 8; nt++) {
                int col = n0 + 8 * nt + cb;
                dst[col]     = pp[nt][0];
                dst[col + 1] = pp[nt][1];
            }
        }
    }
    __syncthreads();
    if (t < 128)
        pooled[t] = part2[t] + part2[128 + t] + part2[256 + t] + part2[384 + t];
    __syncthreads();

    // ---- Phase K: out = pooled @ Wlin + blin, 2 threads per f, dual chains ----
    {
        int f = t & 127, hf = t >> 7;
        const float* pl = pooled + hf * 64;
        const float* wl = Wlin + hf * 64 * 128 + f;
        float o0 = 0.f, o1 = 0.f;
#pragma unroll
        for (int k = 0; k < 32; k++) {
            o0 = fmaf(pl[k],      wl[k * 128],        o0);
            o1 = fmaf(pl[k + 32], wl[(k + 32) * 128], o1);
        }
        part[t] = o0 + o1;
    }
    __syncthreads();
    if (t < 128)
        out[(size_t)g * HID + t] = part[t] + part[t + 128] + blin[t];
}

extern "C" void kernel_launch(void* const* d_in, const int* in_sizes, int n_in,
                              void* d_out, int out_size) {
    const float* x    = (const float*)d_in[0];
    const int*   ei   = (const int*)  d_in[1];
    const float* W1   = (const float*)d_in[3];
    const float* b1   = (const float*)d_in[4];
    const float* Ws   = (const float*)d_in[5];
    const float* bs   = (const float*)d_in[6];
    const float* Wlin = (const float*)d_in[7];
    const float* blin = (const float*)d_in[8];
    float* out = (float*)d_out;

    const int E = in_sizes[1] / 2;
    const int* esrc = ei;
    const int* edst = ei + E;

    cudaFuncSetAttribute(sagpool_fused_kernel,
                         cudaFuncAttributeMaxDynamicSharedMemorySize, SMEM_BYTES);
    sagpool_fused_kernel<<<NB, 256, SMEM_BYTES>>>(
        x, esrc, edst, W1, b1, Ws, bs, Wlin, blin, out);
}